// round 15
// baseline (speedup 1.0000x reference)
#include <cuda_runtime.h>
#include <cstdint>

#define BATCH 4
#define NPTS  8192
#define KNN   16
#define NB    (BATCH * NPTS)
#define EPSV  1e-5f

// ---------------- scratch (device globals: no allocation allowed) ----------
__device__ int   g_idx[NB * KNN];                 // knn indices (within batch)
__device__ float g_PF[(size_t)NB * 128];          // per-point: [Pg(64) | F2(64)]
__device__ float g_CT[(size_t)NB * 128];          // per-point center: [Gc(64) | Sc(64)]

// ---------------- helpers ----------------------------------------------------
__device__ __forceinline__ unsigned long long pk2(float a, float b) {
    unsigned long long r;
    asm("mov.b64 %0, {%1, %2};" : "=l"(r) : "f"(a), "f"(b));
    return r;
}
__device__ __forceinline__ void fma2(unsigned long long& acc,
                                     unsigned long long a, unsigned long long b) {
    asm("fma.rn.f32x2 %0, %1, %2, %0;" : "+l"(acc) : "l"(a), "l"(b));
}
__device__ __forceinline__ unsigned long long fma2d(unsigned long long a,
                                                    unsigned long long b,
                                                    unsigned long long c) {
    unsigned long long r;
    asm("fma.rn.f32x2 %0, %1, %2, %3;" : "=l"(r) : "l"(a), "l"(b), "l"(c));
    return r;
}
__device__ __forceinline__ unsigned long long mul2(unsigned long long a,
                                                   unsigned long long b) {
    unsigned long long r;
    asm("mul.rn.f32x2 %0, %1, %2;" : "=l"(r) : "l"(a), "l"(b));
    return r;
}
__device__ __forceinline__ unsigned long long add2(unsigned long long a,
                                                   unsigned long long b) {
    unsigned long long r;
    asm("add.rn.f32x2 %0, %1, %2;" : "=l"(r) : "l"(a), "l"(b));
    return r;
}
__device__ __forceinline__ float hsum2(unsigned long long v) {
    float lo, hi;
    asm("mov.b64 {%0, %1}, %2;" : "=f"(lo), "=f"(hi) : "l"(v));
    return lo + hi;
}
__device__ __forceinline__ uint32_t smem_u32(const void* p) {
    uint32_t a;
    asm("{ .reg .u64 t; cvta.to.shared.u64 t, %1; cvt.u32.u64 %0, t; }"
        : "=r"(a) : "l"(p));
    return a;
}
// monotonic float->uint map (handles tiny negative d from rounding)
__device__ __forceinline__ unsigned ordf(float f) {
    unsigned u = __float_as_uint(f);
    unsigned s = (unsigned)(((int)u) >> 31);
    return u ^ (s | 0x80000000u);
}

// ============================================================================
// Stage A: per-point precompute (decomposed MLP1/MLP2, batchnorm folded).
// (unchanged — 54us, 8% of total)
// ============================================================================
#define PCHUNK 16
__global__ __launch_bounds__(128) void precompute_kernel(
    const float* __restrict__ pts, const float* __restrict__ feat,
    const float* __restrict__ w_geom,
    const float* __restrict__ g1, const float* __restrict__ b1,
    const float* __restrict__ m1, const float* __restrict__ v1,
    const float* __restrict__ w_sem,
    const float* __restrict__ g2, const float* __restrict__ b2,
    const float* __restrict__ m2, const float* __restrict__ v2)
{
    __shared__ float4 wsb4[16 * 64];   // w_b (scaled), layout [c4][o]
    __shared__ float4 wsd4[16 * 64];   // w_a - w_b (scaled)

    const int o  = threadIdx.x & 63;
    const int ph = threadIdx.x >> 6;

    const float s1  = g1[o] / sqrtf(v1[o] + EPSV);
    const float b1e = b1[o] - m1[o] * s1;
    const float s2  = g2[o] / sqrtf(v2[o] + EPSV);
    const float b2e = b2[o] - m2[o] * s2;

    const float wa0 = w_geom[o*6+0], wa1 = w_geom[o*6+1], wa2 = w_geom[o*6+2];
    const float wb0 = w_geom[o*6+3], wb1 = w_geom[o*6+4], wb2 = w_geom[o*6+5];
    const float pw0 = wb0*s1, pw1 = wb1*s1, pw2 = wb2*s1;
    const float cw0 = (wa0-wb0)*s1, cw1 = (wa1-wb1)*s1, cw2 = (wa2-wb2)*s1;

#pragma unroll
    for (int i = 0; i < 8; ++i) {
        const int c4 = ph * 8 + i;
        float4 wa = *reinterpret_cast<const float4*>(&w_sem[o*128 + c4*4]);
        float4 wb = *reinterpret_cast<const float4*>(&w_sem[o*128 + 64 + c4*4]);
        wsb4[c4*64 + o] = make_float4(wb.x*s2, wb.y*s2, wb.z*s2, wb.w*s2);
        wsd4[c4*64 + o] = make_float4((wa.x-wb.x)*s2, (wa.y-wb.y)*s2,
                                      (wa.z-wb.z)*s2, (wa.w-wb.w)*s2);
    }
    __syncthreads();

    const int base = blockIdx.x * PCHUNK;
    for (int grp = 0; grp < 2; ++grp) {
        int bn[4];
#pragma unroll
        for (int q = 0; q < 4; ++q) bn[q] = base + ph + 2 * (grp * 4 + q);

        float pg[4], gc[4];
        const float4* f4[4];
#pragma unroll
        for (int q = 0; q < 4; ++q) {
            const float x = __ldg(&pts[bn[q]*3+0]);
            const float y = __ldg(&pts[bn[q]*3+1]);
            const float z = __ldg(&pts[bn[q]*3+2]);
            pg[q] = x*pw0 + y*pw1 + z*pw2;
            gc[q] = x*cw0 + y*cw1 + z*cw2 + b1e;
            f4[q] = reinterpret_cast<const float4*>(feat + (size_t)bn[q] * 64);
        }

        unsigned long long aF0[4], aF1[4], aS0[4], aS1[4];
#pragma unroll
        for (int q = 0; q < 4; ++q) { aF0[q]=0; aF1[q]=0; aS0[q]=0; aS1[q]=0; }

#pragma unroll 4
        for (int c4 = 0; c4 < 16; ++c4) {
            ulonglong2 wv = *reinterpret_cast<const ulonglong2*>(&wsb4[c4*64 + o]);
            ulonglong2 dv = *reinterpret_cast<const ulonglong2*>(&wsd4[c4*64 + o]);
#pragma unroll
            for (int q = 0; q < 4; ++q) {
                float4 f = __ldg(&f4[q][c4]);
                unsigned long long fe = pk2(f.x, f.y);
                unsigned long long fo = pk2(f.z, f.w);
                fma2(aF0[q], fe, wv.x); fma2(aF1[q], fo, wv.y);
                fma2(aS0[q], fe, dv.x); fma2(aS1[q], fo, dv.y);
            }
        }
#pragma unroll
        for (int q = 0; q < 4; ++q) {
            const float F2v = hsum2(aF0[q]) + hsum2(aF1[q]);
            const float Scv = hsum2(aS0[q]) + hsum2(aS1[q]) + b2e;
            float* pf = g_PF + (size_t)bn[q] * 128;
            float* ct = g_CT + (size_t)bn[q] * 128;
            pf[o]      = pg[q];   pf[64 + o] = F2v;
            ct[o]      = gc[q];   ct[64 + o] = Scv;
        }
    }
}

// ============================================================================
// Stage B: buffered streaming KNN, 4-way split + stable merge. Packed f32x2
// distances (per-lane fp sequence identical to scalar: FMUL,FFMA,FFMA,FADD,
// FFMA -> selection semantics == stable lax.top_k). Ballot/flush check only
// every 2 chunks (16 candidates): after any check all lanes have cnt<=3,
// growth <=16 -> max 19 <= BCAP 20.
// ============================================================================
#define SPLITS 4
#define QPB    64
#define RANGE  (NPTS / SPLITS)      // 2048
#define TILE   256
#define BCAP   20                    // per-thread buffer slots

#define KFLUSH() do {                                                        \
    for (int i_ = 0; i_ < cnt; ++i_) {                                       \
        int j_; unsigned db_;                                                \
        asm volatile("ld.shared.v2.b32 {%0, %1}, [%2];"                      \
                     : "=r"(j_), "=r"(db_) : "r"(bufa + i_ * 2048));         \
        float d_ = __uint_as_float(db_);                                     \
        if (d_ < bd[15]) {                                                   \
            bd[15] = d_; bi[15] = j_;                                        \
            _Pragma("unroll")                                                \
            for (int s_ = 15; s_ > 0; --s_) {                                \
                if (bd[s_] < bd[s_-1]) {                                     \
                    float td_ = bd[s_]; bd[s_] = bd[s_-1]; bd[s_-1] = td_;   \
                    int   ti_ = bi[s_]; bi[s_] = bi[s_-1]; bi[s_-1] = ti_;   \
                }                                                            \
            }                                                                \
        }                                                                    \
    }                                                                        \
    cnt = 0; thr = bd[15];                                                   \
} while (0)

__global__ __launch_bounds__(256) void knn_kernel(const float* __restrict__ pts)
{
    __shared__ float4             cxy[SPLITS][TILE/2];         // 8 KB
    __shared__ float4             czw[SPLITS][TILE/2];         // 8 KB
    __shared__ unsigned long long buf[BCAP * 256];             // 40 KB (reused for merge)

    const int tid = threadIdx.x;
    const int g   = tid >> 6;                     // split 0..3
    const int ql  = tid & 63;                     // local query
    const int b   = blockIdx.x >> 7;              // 128 blocks per batch
    const int n   = ((blockIdx.x & 127) << 6) + ql;
    const float* pb = pts + (size_t)b * NPTS * 3;

    const float qx = pb[n*3+0], qy = pb[n*3+1], qz = pb[n*3+2];
    const float qsq = qx*qx + qy*qy + qz*qz;

    const unsigned long long qx2 = pk2(qx, qx);
    const unsigned long long qy2 = pk2(qy, qy);
    const unsigned long long qz2 = pk2(qz, qz);
    const unsigned long long qs2 = pk2(qsq, qsq);
    const unsigned long long m22 = pk2(-2.0f, -2.0f);

    float bd[KNN]; int bi[KNN];
#pragma unroll
    for (int i = 0; i < KNN; ++i) { bd[i] = 3.4e38f; bi[i] = 0; }

    const uint32_t bufa = smem_u32(buf) + tid * 8;
    int   cnt = 0;
    float thr = 3.4e38f;
    const int jbase = g * RANGE;

    for (int t = 0; t < RANGE / TILE; ++t) {
        __syncthreads();
        {   // fill this split's SoA tile: each of 64 threads loads 4 points
            const int src = jbase + t * TILE;
            const float* s = pb + (size_t)(src + ql * 4) * 3;
            float4 A = *reinterpret_cast<const float4*>(s);      // x0 y0 z0 x1
            float4 B = *reinterpret_cast<const float4*>(s + 4);  // y1 z1 x2 y2
            float4 C = *reinterpret_cast<const float4*>(s + 8);  // z2 x3 y3 z3
            const float sq0 = A.x*A.x + A.y*A.y + A.z*A.z;
            const float sq1 = A.w*A.w + B.x*B.x + B.y*B.y;
            const float sq2 = B.z*B.z + B.w*B.w + C.x*C.x;
            const float sq3 = C.y*C.y + C.z*C.z + C.w*C.w;
            cxy[g][ql*2+0] = make_float4(A.x, A.w, A.y, B.x);    // cx0 cx1 cy0 cy1
            czw[g][ql*2+0] = make_float4(A.z, B.y, sq0, sq1);    // cz0 cz1 sq0 sq1
            cxy[g][ql*2+1] = make_float4(B.z, C.y, B.w, C.z);    // cx2 cx3 cy2 cy3
            czw[g][ql*2+1] = make_float4(C.x, C.w, sq2, sq3);    // cz2 cz3 sq2 sq3
        }
        __syncthreads();
        const int jb = jbase + t * TILE;

#pragma unroll 2
        for (int c8 = 0; c8 < TILE / 8; ++c8) {
            // 1) distances: 4 independent packed pairs (8 candidates)
            float dv[8];
#pragma unroll
            for (int pp = 0; pp < 4; ++pp) {
                const int pr = c8 * 4 + pp;
                const float4 xy = cxy[g][pr];
                const float4 zw = czw[g][pr];
                unsigned long long dot = mul2(pk2(xy.x, xy.y), qx2);
                dot = fma2d(pk2(xy.z, xy.w), qy2, dot);
                dot = fma2d(pk2(zw.x, zw.y), qz2, dot);
                const unsigned long long tt = add2(qs2, pk2(zw.z, zw.w));
                const unsigned long long d2 = fma2d(dot, m22, tt);
                asm("mov.b64 {%0, %1}, %2;"
                    : "=f"(dv[2*pp]), "=f"(dv[2*pp+1]) : "l"(d2));
            }
            // 2) insert mask (no cross-candidate serial chain)
            unsigned m = 0;
#pragma unroll
            for (int jj = 0; jj < 8; ++jj)
                m |= (dv[jj] < thr) ? (1u << jj) : 0u;
            // 3) offsets via prefix-popcount; predicated v2 stores
#pragma unroll
            for (int jj = 0; jj < 8; ++jj) {
                const int off = cnt + __popc(m & ((1u << jj) - 1u));
                const uint32_t a = bufa + (uint32_t)off * 2048;
                asm volatile(
                    "{ .reg .pred p; setp.lt.f32 p, %0, %1;"
                    " @p st.shared.v2.b32 [%2], {%3, %4}; }"
                    :: "f"(dv[jj]), "f"(thr), "r"(a),
                       "r"(jb + c8 * 8 + jj), "r"(__float_as_uint(dv[jj])));
            }
            cnt += __popc(m);
            // collective check only every 2nd chunk (16 candidates)
            if (c8 & 1) {
                if (__ballot_sync(0xffffffffu, cnt >= 4)) { KFLUSH(); }
            }
        }
    }
    KFLUSH();

    // write sorted partial list as packed (ordered-d, idx) keys (reuse buf)
    __syncthreads();
#pragma unroll
    for (int k = 0; k < KNN; ++k)
        buf[k * 256 + tid] =
            (((unsigned long long)ordf(bd[k])) << 32) | (unsigned)bi[k];
    __syncthreads();

    // stable 4-way merge: threads 0..63 (one per query)
    if (tid < QPB) {
        const unsigned long long MX = ~0ull;
        unsigned long long h0 = buf[tid];
        unsigned long long h1 = buf[64 + tid];
        unsigned long long h2 = buf[128 + tid];
        unsigned long long h3 = buf[192 + tid];
        int p0 = 1, p1 = 1, p2 = 1, p3 = 1;
        int* op = g_idx + ((size_t)b * NPTS + n) * KNN;
#pragma unroll
        for (int k = 0; k < KNN; ++k) {
            unsigned long long m01 = (h0 < h1) ? h0 : h1;
            unsigned long long m23 = (h2 < h3) ? h2 : h3;
            unsigned long long m   = (m01 < m23) ? m01 : m23;
            op[k] = (int)(unsigned)m;
            if (m == h0)      { h0 = (p0 < 16) ? buf[p0*256 +       tid] : MX; ++p0; }
            else if (m == h1) { h1 = (p1 < 16) ? buf[p1*256 +  64 + tid] : MX; ++p1; }
            else if (m == h2) { h2 = (p2 < 16) ? buf[p2*256 + 128 + tid] : MX; ++p2; }
            else              { h3 = (p3 < 16) ? buf[p3*256 + 192 + tid] : MX; ++p3; }
        }
    }
}

// ============================================================================
// Stage C: gather PF[j] + CT[n], relu -> act; fused GEMM on packed f32x2.
// o2 = tid&31 computes outputs (o2, o2+32); grp = tid>>5 handles a quad of
// k's for both points -> each av LDS.128 feeds 4 FFMA2 (FMA-bound).
// FPTS=8: 4096 blocks -> 6.9 waves, ~2% tail (was 3.46 waves, ~15% tail).
// ============================================================================
#define FPTS 8
__global__ __launch_bounds__(128) void fuse_kernel(
    const float* __restrict__ w_fuse,
    const float* __restrict__ g3, const float* __restrict__ b3,
    const float* __restrict__ m3, const float* __restrict__ v3,
    float* __restrict__ out)
{
    __shared__ float4 wf4[32 * 64];      // 32 KB: scaled w_fuse, [c4][o]
    __shared__ float4 act4[2][16 * 32];  // 16 KB: act[pt][k][c4]
    __shared__ float  red[512];          // [pt][grp][oh][o2]
    __shared__ float  b3e_s[64];

    const int tid  = threadIdx.x;
    const int o    = tid & 63;
    const int half = tid >> 6;

    {   // stage weights (fold batchnorm scale into w_fuse)
        const float s3 = g3[o] / sqrtf(v3[o] + EPSV);
        if (half == 0) b3e_s[o] = b3[o] - m3[o] * s3;
#pragma unroll
        for (int i = 0; i < 16; ++i) {
            const int c4 = half * 16 + i;
            float4 w = *reinterpret_cast<const float4*>(&w_fuse[o*128 + c4*4]);
            wf4[c4*64 + o] = make_float4(w.x*s3, w.y*s3, w.z*s3, w.w*s3);
        }
    }
    __syncthreads();

    const int o2  = tid & 31;
    const int grp = tid >> 5;
    const int k0  = grp * 4;
    const float b3e0 = b3e_s[o2];
    const float b3e1 = b3e_s[o2 + 32];

    const int base = blockIdx.x * FPTS;

    for (int p = 0; p < FPTS; p += 2) {
        const int bn = base + p;

        // ---- build activation tiles for 2 points
        {
            const int k  = tid >> 3;
            const int cg = (tid & 7) * 4;
            const int bb = bn >> 13;                       // bn / NPTS
#pragma unroll
            for (int pt = 0; pt < 2; ++pt) {
                const int j = g_idx[(bn + pt)*KNN + k];
                const float4* pfr = reinterpret_cast<const float4*>(
                                        g_PF + ((size_t)(bb * NPTS + j)) * 128);
                const float4* ctr = reinterpret_cast<const float4*>(
                                        g_CT + (size_t)(bn + pt) * 128);
#pragma unroll
                for (int q = 0; q < 4; ++q) {
                    float4 a = pfr[cg + q];
                    float4 c = ctr[cg + q];
                    act4[pt][k*32 + cg + q] = make_float4(
                        fmaxf(a.x + c.x, 0.f), fmaxf(a.y + c.y, 0.f),
                        fmaxf(a.z + c.z, 0.f), fmaxf(a.w + c.w, 0.f));
                }
            }
        }
        __syncthreads();

        // ---- GEMM: 2 o's x 2 pts x 4 k's per thread, merged e/o accumulators
        unsigned long long acc[2][2][4];   // [oh][pt][kk]
#pragma unroll
        for (int oh = 0; oh < 2; ++oh)
#pragma unroll
            for (int pt = 0; pt < 2; ++pt)
#pragma unroll
                for (int kk = 0; kk < 4; ++kk) acc[oh][pt][kk] = 0ull;

#pragma unroll 4
        for (int c4 = 0; c4 < 32; ++c4) {
            ulonglong2 wv0 = *reinterpret_cast<const ulonglong2*>(&wf4[c4*64 + o2]);
            ulonglong2 wv1 = *reinterpret_cast<const ulonglong2*>(&wf4[c4*64 + o2 + 32]);
#pragma unroll
            for (int pt = 0; pt < 2; ++pt) {
#pragma unroll
                for (int kk = 0; kk < 4; ++kk) {
                    ulonglong2 av = *reinterpret_cast<const ulonglong2*>(
                                        &act4[pt][(k0 + kk)*32 + c4]);
                    fma2(acc[0][pt][kk], av.x, wv0.x);
                    fma2(acc[0][pt][kk], av.y, wv0.y);
                    fma2(acc[1][pt][kk], av.x, wv1.x);
                    fma2(acc[1][pt][kk], av.y, wv1.y);
                }
            }
        }

#pragma unroll
        for (int oh = 0; oh < 2; ++oh) {
            const float b3e = oh ? b3e1 : b3e0;
#pragma unroll
            for (int pt = 0; pt < 2; ++pt) {
                float mx = 0.f;                            // relu => max >= 0
#pragma unroll
                for (int kk = 0; kk < 4; ++kk)
                    mx = fmaxf(mx, hsum2(acc[oh][pt][kk]) + b3e);
                red[((pt*4 + grp)*2 + oh)*32 + o2] = mx;   // partial (4 k's)
            }
        }
        __syncthreads();

        {   // final max across the 4 k-quads; 128 threads = 2 pts x 64 o
            const int pt  = tid >> 6;
            const int oo  = tid & 63;
            const int ohh = oo >> 5, oo2 = oo & 31;
            float m0 = red[((pt*4 + 0)*2 + ohh)*32 + oo2];
            float m1 = red[((pt*4 + 1)*2 + ohh)*32 + oo2];
            float m2 = red[((pt*4 + 2)*2 + ohh)*32 + oo2];
            float m3v = red[((pt*4 + 3)*2 + ohh)*32 + oo2];
            out[(size_t)(bn + pt) * 64 + oo] =
                fmaxf(fmaxf(m0, m1), fmaxf(m2, m3v));
        }
        __syncthreads();                                   // protect act4/red
    }
}

// ============================================================================
extern "C" void kernel_launch(void* const* d_in, const int* in_sizes, int n_in,
                              void* d_out, int out_size)
{
    const float* pts    = (const float*)d_in[0];
    const float* feat   = (const float*)d_in[1];
    const float* w_geom = (const float*)d_in[2];
    const float* g1 = (const float*)d_in[3];
    const float* b1 = (const float*)d_in[4];
    const float* m1 = (const float*)d_in[5];
    const float* v1 = (const float*)d_in[6];
    const float* w_sem  = (const float*)d_in[7];
    const float* g2 = (const float*)d_in[8];
    const float* b2 = (const float*)d_in[9];
    const float* m2 = (const float*)d_in[10];
    const float* v2 = (const float*)d_in[11];
    const float* w_fuse = (const float*)d_in[12];
    const float* g3 = (const float*)d_in[13];
    const float* b3 = (const float*)d_in[14];
    const float* m3 = (const float*)d_in[15];
    const float* v3 = (const float*)d_in[16];
    float* out = (float*)d_out;

    precompute_kernel<<<NB / PCHUNK, 128>>>(pts, feat, w_geom,
                                            g1, b1, m1, v1,
                                            w_sem, g2, b2, m2, v2);
    knn_kernel<<<NB / QPB, 256>>>(pts);
    fuse_kernel<<<NB / FPTS, 128>>>(w_fuse, g3, b3, m3, v3, out);
}

// round 16
// speedup vs baseline: 1.0512x; 1.0512x over previous
#include <cuda_runtime.h>
#include <cstdint>

#define BATCH 4
#define NPTS  8192
#define KNN   16
#define NB    (BATCH * NPTS)
#define EPSV  1e-5f

// ---------------- scratch (device globals: no allocation allowed) ----------
__device__ int   g_idx[NB * KNN];                 // knn indices (within batch)
__device__ float g_PF[(size_t)NB * 128];          // per-point: [Pg(64) | F2(64)]
__device__ float g_CT[(size_t)NB * 128];          // per-point center: [Gc(64) | Sc(64)]

// ---------------- helpers ----------------------------------------------------
__device__ __forceinline__ unsigned long long pk2(float a, float b) {
    unsigned long long r;
    asm("mov.b64 %0, {%1, %2};" : "=l"(r) : "f"(a), "f"(b));
    return r;
}
__device__ __forceinline__ void fma2(unsigned long long& acc,
                                     unsigned long long a, unsigned long long b) {
    asm("fma.rn.f32x2 %0, %1, %2, %0;" : "+l"(acc) : "l"(a), "l"(b));
}
__device__ __forceinline__ unsigned long long fma2d(unsigned long long a,
                                                    unsigned long long b,
                                                    unsigned long long c) {
    unsigned long long r;
    asm("fma.rn.f32x2 %0, %1, %2, %3;" : "=l"(r) : "l"(a), "l"(b), "l"(c));
    return r;
}
__device__ __forceinline__ unsigned long long mul2(unsigned long long a,
                                                   unsigned long long b) {
    unsigned long long r;
    asm("mul.rn.f32x2 %0, %1, %2;" : "=l"(r) : "l"(a), "l"(b));
    return r;
}
__device__ __forceinline__ unsigned long long add2(unsigned long long a,
                                                   unsigned long long b) {
    unsigned long long r;
    asm("add.rn.f32x2 %0, %1, %2;" : "=l"(r) : "l"(a), "l"(b));
    return r;
}
__device__ __forceinline__ float hsum2(unsigned long long v) {
    float lo, hi;
    asm("mov.b64 {%0, %1}, %2;" : "=f"(lo), "=f"(hi) : "l"(v));
    return lo + hi;
}
__device__ __forceinline__ uint32_t smem_u32(const void* p) {
    uint32_t a;
    asm("{ .reg .u64 t; cvta.to.shared.u64 t, %1; cvt.u32.u64 %0, t; }"
        : "=r"(a) : "l"(p));
    return a;
}
// monotonic float->uint map (handles tiny negative d from rounding)
__device__ __forceinline__ unsigned ordf(float f) {
    unsigned u = __float_as_uint(f);
    unsigned s = (unsigned)(((int)u) >> 31);
    return u ^ (s | 0x80000000u);
}

// ============================================================================
// Stage A: per-point precompute (decomposed MLP1/MLP2, batchnorm folded).
// Triggers programmatic launch completion at entry so the (independent) KNN
// kernel co-schedules into the SM capacity precompute doesn't use.
// ============================================================================
#define PCHUNK 16
__global__ __launch_bounds__(128) void precompute_kernel(
    const float* __restrict__ pts, const float* __restrict__ feat,
    const float* __restrict__ w_geom,
    const float* __restrict__ g1, const float* __restrict__ b1,
    const float* __restrict__ m1, const float* __restrict__ v1,
    const float* __restrict__ w_sem,
    const float* __restrict__ g2, const float* __restrict__ b2,
    const float* __restrict__ m2, const float* __restrict__ v2)
{
    cudaTriggerProgrammaticLaunchCompletion();   // let knn start now

    __shared__ float4 wsb4[16 * 64];   // w_b (scaled), layout [c4][o]
    __shared__ float4 wsd4[16 * 64];   // w_a - w_b (scaled)

    const int o  = threadIdx.x & 63;
    const int ph = threadIdx.x >> 6;

    const float s1  = g1[o] / sqrtf(v1[o] + EPSV);
    const float b1e = b1[o] - m1[o] * s1;
    const float s2  = g2[o] / sqrtf(v2[o] + EPSV);
    const float b2e = b2[o] - m2[o] * s2;

    const float wa0 = w_geom[o*6+0], wa1 = w_geom[o*6+1], wa2 = w_geom[o*6+2];
    const float wb0 = w_geom[o*6+3], wb1 = w_geom[o*6+4], wb2 = w_geom[o*6+5];
    const float pw0 = wb0*s1, pw1 = wb1*s1, pw2 = wb2*s1;
    const float cw0 = (wa0-wb0)*s1, cw1 = (wa1-wb1)*s1, cw2 = (wa2-wb2)*s1;

#pragma unroll
    for (int i = 0; i < 8; ++i) {
        const int c4 = ph * 8 + i;
        float4 wa = *reinterpret_cast<const float4*>(&w_sem[o*128 + c4*4]);
        float4 wb = *reinterpret_cast<const float4*>(&w_sem[o*128 + 64 + c4*4]);
        wsb4[c4*64 + o] = make_float4(wb.x*s2, wb.y*s2, wb.z*s2, wb.w*s2);
        wsd4[c4*64 + o] = make_float4((wa.x-wb.x)*s2, (wa.y-wb.y)*s2,
                                      (wa.z-wb.z)*s2, (wa.w-wb.w)*s2);
    }
    __syncthreads();

    const int base = blockIdx.x * PCHUNK;
    for (int grp = 0; grp < 2; ++grp) {
        int bn[4];
#pragma unroll
        for (int q = 0; q < 4; ++q) bn[q] = base + ph + 2 * (grp * 4 + q);

        float pg[4], gc[4];
        const float4* f4[4];
#pragma unroll
        for (int q = 0; q < 4; ++q) {
            const float x = __ldg(&pts[bn[q]*3+0]);
            const float y = __ldg(&pts[bn[q]*3+1]);
            const float z = __ldg(&pts[bn[q]*3+2]);
            pg[q] = x*pw0 + y*pw1 + z*pw2;
            gc[q] = x*cw0 + y*cw1 + z*cw2 + b1e;
            f4[q] = reinterpret_cast<const float4*>(feat + (size_t)bn[q] * 64);
        }

        unsigned long long aF0[4], aF1[4], aS0[4], aS1[4];
#pragma unroll
        for (int q = 0; q < 4; ++q) { aF0[q]=0; aF1[q]=0; aS0[q]=0; aS1[q]=0; }

#pragma unroll 4
        for (int c4 = 0; c4 < 16; ++c4) {
            ulonglong2 wv = *reinterpret_cast<const ulonglong2*>(&wsb4[c4*64 + o]);
            ulonglong2 dv = *reinterpret_cast<const ulonglong2*>(&wsd4[c4*64 + o]);
#pragma unroll
            for (int q = 0; q < 4; ++q) {
                float4 f = __ldg(&f4[q][c4]);
                unsigned long long fe = pk2(f.x, f.y);
                unsigned long long fo = pk2(f.z, f.w);
                fma2(aF0[q], fe, wv.x); fma2(aF1[q], fo, wv.y);
                fma2(aS0[q], fe, dv.x); fma2(aS1[q], fo, dv.y);
            }
        }
#pragma unroll
        for (int q = 0; q < 4; ++q) {
            const float F2v = hsum2(aF0[q]) + hsum2(aF1[q]);
            const float Scv = hsum2(aS0[q]) + hsum2(aS1[q]) + b2e;
            float* pf = g_PF + (size_t)bn[q] * 128;
            float* ct = g_CT + (size_t)bn[q] * 128;
            pf[o]      = pg[q];   pf[64 + o] = F2v;
            ct[o]      = gc[q];   ct[64 + o] = Scv;
        }
    }
}

// ============================================================================
// Stage B: buffered streaming KNN (exact R14 version: BCAP 16, 48 KB smem =
// 4 blocks/SM, ballot every 8 candidates). Packed f32x2 distances; per-lane
// fp sequence identical to scalar -> selection semantics == stable lax.top_k.
// Independent of precompute (reads only pts), so it launches with PDL.
// ============================================================================
#define SPLITS 4
#define QPB    64
#define RANGE  (NPTS / SPLITS)      // 2048
#define TILE   256
#define BCAP   16                    // per-thread buffer slots

#define KFLUSH() do {                                                        \
    for (int i_ = 0; i_ < cnt; ++i_) {                                       \
        int j_; unsigned db_;                                                \
        asm volatile("ld.shared.v2.b32 {%0, %1}, [%2];"                      \
                     : "=r"(j_), "=r"(db_) : "r"(bufa + i_ * 2048));         \
        float d_ = __uint_as_float(db_);                                     \
        if (d_ < bd[15]) {                                                   \
            bd[15] = d_; bi[15] = j_;                                        \
            _Pragma("unroll")                                                \
            for (int s_ = 15; s_ > 0; --s_) {                                \
                if (bd[s_] < bd[s_-1]) {                                     \
                    float td_ = bd[s_]; bd[s_] = bd[s_-1]; bd[s_-1] = td_;   \
                    int   ti_ = bi[s_]; bi[s_] = bi[s_-1]; bi[s_-1] = ti_;   \
                }                                                            \
            }                                                                \
        }                                                                    \
    }                                                                        \
    cnt = 0; thr = bd[15];                                                   \
} while (0)

__global__ __launch_bounds__(256) void knn_kernel(const float* __restrict__ pts)
{
    __shared__ float4             cxy[SPLITS][TILE/2];         // 8 KB
    __shared__ float4             czw[SPLITS][TILE/2];         // 8 KB
    __shared__ unsigned long long buf[BCAP * 256];             // 32 KB (reused for merge)

    const int tid = threadIdx.x;
    const int g   = tid >> 6;                     // split 0..3
    const int ql  = tid & 63;                     // local query
    const int b   = blockIdx.x >> 7;              // 128 blocks per batch
    const int n   = ((blockIdx.x & 127) << 6) + ql;
    const float* pb = pts + (size_t)b * NPTS * 3;

    const float qx = pb[n*3+0], qy = pb[n*3+1], qz = pb[n*3+2];
    const float qsq = qx*qx + qy*qy + qz*qz;

    const unsigned long long qx2 = pk2(qx, qx);
    const unsigned long long qy2 = pk2(qy, qy);
    const unsigned long long qz2 = pk2(qz, qz);
    const unsigned long long qs2 = pk2(qsq, qsq);
    const unsigned long long m22 = pk2(-2.0f, -2.0f);

    float bd[KNN]; int bi[KNN];
#pragma unroll
    for (int i = 0; i < KNN; ++i) { bd[i] = 3.4e38f; bi[i] = 0; }

    const uint32_t bufa = smem_u32(buf) + tid * 8;
    int   cnt = 0;
    float thr = 3.4e38f;
    const int jbase = g * RANGE;

    for (int t = 0; t < RANGE / TILE; ++t) {
        __syncthreads();
        {   // fill this split's SoA tile: each of 64 threads loads 4 points
            const int src = jbase + t * TILE;
            const float* s = pb + (size_t)(src + ql * 4) * 3;
            float4 A = *reinterpret_cast<const float4*>(s);      // x0 y0 z0 x1
            float4 B = *reinterpret_cast<const float4*>(s + 4);  // y1 z1 x2 y2
            float4 C = *reinterpret_cast<const float4*>(s + 8);  // z2 x3 y3 z3
            const float sq0 = A.x*A.x + A.y*A.y + A.z*A.z;
            const float sq1 = A.w*A.w + B.x*B.x + B.y*B.y;
            const float sq2 = B.z*B.z + B.w*B.w + C.x*C.x;
            const float sq3 = C.y*C.y + C.z*C.z + C.w*C.w;
            cxy[g][ql*2+0] = make_float4(A.x, A.w, A.y, B.x);    // cx0 cx1 cy0 cy1
            czw[g][ql*2+0] = make_float4(A.z, B.y, sq0, sq1);    // cz0 cz1 sq0 sq1
            cxy[g][ql*2+1] = make_float4(B.z, C.y, B.w, C.z);    // cx2 cx3 cy2 cy3
            czw[g][ql*2+1] = make_float4(C.x, C.w, sq2, sq3);    // cz2 cz3 sq2 sq3
        }
        __syncthreads();
        const int jb = jbase + t * TILE;

        for (int c8 = 0; c8 < TILE / 8; ++c8) {
            // 1) distances: 4 independent packed pairs (8 candidates)
            float dv[8];
#pragma unroll
            for (int pp = 0; pp < 4; ++pp) {
                const int pr = c8 * 4 + pp;
                const float4 xy = cxy[g][pr];
                const float4 zw = czw[g][pr];
                unsigned long long dot = mul2(pk2(xy.x, xy.y), qx2);
                dot = fma2d(pk2(xy.z, xy.w), qy2, dot);
                dot = fma2d(pk2(zw.x, zw.y), qz2, dot);
                const unsigned long long tt = add2(qs2, pk2(zw.z, zw.w));
                const unsigned long long d2 = fma2d(dot, m22, tt);
                asm("mov.b64 {%0, %1}, %2;"
                    : "=f"(dv[2*pp]), "=f"(dv[2*pp+1]) : "l"(d2));
            }
            // 2) insert mask (no cross-candidate serial chain)
            unsigned m = 0;
#pragma unroll
            for (int jj = 0; jj < 8; ++jj)
                m |= (dv[jj] < thr) ? (1u << jj) : 0u;
            // 3) offsets via prefix-popcount; predicated v2 stores
#pragma unroll
            for (int jj = 0; jj < 8; ++jj) {
                const int off = cnt + __popc(m & ((1u << jj) - 1u));
                const uint32_t a = bufa + (uint32_t)off * 2048;
                asm volatile(
                    "{ .reg .pred p; setp.lt.f32 p, %0, %1;"
                    " @p st.shared.v2.b32 [%2], {%3, %4}; }"
                    :: "f"(dv[jj]), "f"(thr), "r"(a),
                       "r"(jb + c8 * 8 + jj), "r"(__float_as_uint(dv[jj])));
            }
            cnt += __popc(m);
            if (__ballot_sync(0xffffffffu, cnt >= 8)) { KFLUSH(); }
        }
    }
    KFLUSH();

    // write sorted partial list as packed (ordered-d, idx) keys (reuse buf)
    __syncthreads();
#pragma unroll
    for (int k = 0; k < KNN; ++k)
        buf[k * 256 + tid] =
            (((unsigned long long)ordf(bd[k])) << 32) | (unsigned)bi[k];
    __syncthreads();

    // stable 4-way merge: threads 0..63 (one per query)
    if (tid < QPB) {
        const unsigned long long MX = ~0ull;
        unsigned long long h0 = buf[tid];
        unsigned long long h1 = buf[64 + tid];
        unsigned long long h2 = buf[128 + tid];
        unsigned long long h3 = buf[192 + tid];
        int p0 = 1, p1 = 1, p2 = 1, p3 = 1;
        int* op = g_idx + ((size_t)b * NPTS + n) * KNN;
#pragma unroll
        for (int k = 0; k < KNN; ++k) {
            unsigned long long m01 = (h0 < h1) ? h0 : h1;
            unsigned long long m23 = (h2 < h3) ? h2 : h3;
            unsigned long long m   = (m01 < m23) ? m01 : m23;
            op[k] = (int)(unsigned)m;
            if (m == h0)      { h0 = (p0 < 16) ? buf[p0*256 +       tid] : MX; ++p0; }
            else if (m == h1) { h1 = (p1 < 16) ? buf[p1*256 +  64 + tid] : MX; ++p1; }
            else if (m == h2) { h2 = (p2 < 16) ? buf[p2*256 + 128 + tid] : MX; ++p2; }
            else              { h3 = (p3 < 16) ? buf[p3*256 + 192 + tid] : MX; ++p3; }
        }
    }
}

// ============================================================================
// Stage C: gather PF[j] + CT[n], relu -> act; fused GEMM on packed f32x2.
// (exact R14 version: FPTS=16, o-pair mapping -> FMA-bound)
// ============================================================================
#define FPTS 16
__global__ __launch_bounds__(128) void fuse_kernel(
    const float* __restrict__ w_fuse,
    const float* __restrict__ g3, const float* __restrict__ b3,
    const float* __restrict__ m3, const float* __restrict__ v3,
    float* __restrict__ out)
{
    __shared__ float4 wf4[32 * 64];      // 32 KB: scaled w_fuse, [c4][o]
    __shared__ float4 act4[2][16 * 32];  // 16 KB: act[pt][k][c4]
    __shared__ float  red[512];          // [pt][grp][oh][o2]
    __shared__ float  b3e_s[64];

    const int tid  = threadIdx.x;
    const int o    = tid & 63;
    const int half = tid >> 6;

    {   // stage weights (fold batchnorm scale into w_fuse)
        const float s3 = g3[o] / sqrtf(v3[o] + EPSV);
        if (half == 0) b3e_s[o] = b3[o] - m3[o] * s3;
#pragma unroll
        for (int i = 0; i < 16; ++i) {
            const int c4 = half * 16 + i;
            float4 w = *reinterpret_cast<const float4*>(&w_fuse[o*128 + c4*4]);
            wf4[c4*64 + o] = make_float4(w.x*s3, w.y*s3, w.z*s3, w.w*s3);
        }
    }
    __syncthreads();

    const int o2  = tid & 31;
    const int grp = tid >> 5;
    const int k0  = grp * 4;
    const float b3e0 = b3e_s[o2];
    const float b3e1 = b3e_s[o2 + 32];

    const int base = blockIdx.x * FPTS;

    for (int p = 0; p < FPTS; p += 2) {
        const int bn = base + p;

        // ---- build activation tiles for 2 points
        {
            const int k  = tid >> 3;
            const int cg = (tid & 7) * 4;
            const int bb = bn >> 13;                       // bn / NPTS
#pragma unroll
            for (int pt = 0; pt < 2; ++pt) {
                const int j = g_idx[(bn + pt)*KNN + k];
                const float4* pfr = reinterpret_cast<const float4*>(
                                        g_PF + ((size_t)(bb * NPTS + j)) * 128);
                const float4* ctr = reinterpret_cast<const float4*>(
                                        g_CT + (size_t)(bn + pt) * 128);
#pragma unroll
                for (int q = 0; q < 4; ++q) {
                    float4 a = pfr[cg + q];
                    float4 c = ctr[cg + q];
                    act4[pt][k*32 + cg + q] = make_float4(
                        fmaxf(a.x + c.x, 0.f), fmaxf(a.y + c.y, 0.f),
                        fmaxf(a.z + c.z, 0.f), fmaxf(a.w + c.w, 0.f));
                }
            }
        }
        __syncthreads();

        // ---- GEMM: 2 o's x 2 pts x 4 k's per thread, merged e/o accumulators
        unsigned long long acc[2][2][4];   // [oh][pt][kk]
#pragma unroll
        for (int oh = 0; oh < 2; ++oh)
#pragma unroll
            for (int pt = 0; pt < 2; ++pt)
#pragma unroll
                for (int kk = 0; kk < 4; ++kk) acc[oh][pt][kk] = 0ull;

#pragma unroll 4
        for (int c4 = 0; c4 < 32; ++c4) {
            ulonglong2 wv0 = *reinterpret_cast<const ulonglong2*>(&wf4[c4*64 + o2]);
            ulonglong2 wv1 = *reinterpret_cast<const ulonglong2*>(&wf4[c4*64 + o2 + 32]);
#pragma unroll
            for (int pt = 0; pt < 2; ++pt) {
#pragma unroll
                for (int kk = 0; kk < 4; ++kk) {
                    ulonglong2 av = *reinterpret_cast<const ulonglong2*>(
                                        &act4[pt][(k0 + kk)*32 + c4]);
                    fma2(acc[0][pt][kk], av.x, wv0.x);
                    fma2(acc[0][pt][kk], av.y, wv0.y);
                    fma2(acc[1][pt][kk], av.x, wv1.x);
                    fma2(acc[1][pt][kk], av.y, wv1.y);
                }
            }
        }

#pragma unroll
        for (int oh = 0; oh < 2; ++oh) {
            const float b3e = oh ? b3e1 : b3e0;
#pragma unroll
            for (int pt = 0; pt < 2; ++pt) {
                float mx = 0.f;                            // relu => max >= 0
#pragma unroll
                for (int kk = 0; kk < 4; ++kk)
                    mx = fmaxf(mx, hsum2(acc[oh][pt][kk]) + b3e);
                red[((pt*4 + grp)*2 + oh)*32 + o2] = mx;   // partial (4 k's)
            }
        }
        __syncthreads();

        {   // final max across the 4 k-quads; 128 threads = 2 pts x 64 o
            const int pt  = tid >> 6;
            const int oo  = tid & 63;
            const int ohh = oo >> 5, oo2 = oo & 31;
            float m0 = red[((pt*4 + 0)*2 + ohh)*32 + oo2];
            float m1 = red[((pt*4 + 1)*2 + ohh)*32 + oo2];
            float m2 = red[((pt*4 + 2)*2 + ohh)*32 + oo2];
            float m3v = red[((pt*4 + 3)*2 + ohh)*32 + oo2];
            out[(size_t)(bn + pt) * 64 + oo] =
                fmaxf(fmaxf(m0, m1), fmaxf(m2, m3v));
        }
        __syncthreads();                                   // protect act4/red
    }
}

// ============================================================================
extern "C" void kernel_launch(void* const* d_in, const int* in_sizes, int n_in,
                              void* d_out, int out_size)
{
    const float* pts    = (const float*)d_in[0];
    const float* feat   = (const float*)d_in[1];
    const float* w_geom = (const float*)d_in[2];
    const float* g1 = (const float*)d_in[3];
    const float* b1 = (const float*)d_in[4];
    const float* m1 = (const float*)d_in[5];
    const float* v1 = (const float*)d_in[6];
    const float* w_sem  = (const float*)d_in[7];
    const float* g2 = (const float*)d_in[8];
    const float* b2 = (const float*)d_in[9];
    const float* m2 = (const float*)d_in[10];
    const float* v2 = (const float*)d_in[11];
    const float* w_fuse = (const float*)d_in[12];
    const float* g3 = (const float*)d_in[13];
    const float* b3 = (const float*)d_in[14];
    const float* m3 = (const float*)d_in[15];
    const float* v3 = (const float*)d_in[16];
    float* out = (float*)d_out;

    // 1) precompute (triggers PDL completion at CTA entry)
    precompute_kernel<<<NB / PCHUNK, 128>>>(pts, feat, w_geom,
                                            g1, b1, m1, v1,
                                            w_sem, g2, b2, m2, v2);

    // 2) knn: independent of precompute -> programmatic dependent launch so
    //    it co-schedules into leftover SM capacity immediately.
    {
        cudaLaunchConfig_t cfg = {};
        cfg.gridDim  = dim3(NB / QPB);
        cfg.blockDim = dim3(256);
        cfg.dynamicSmemBytes = 0;
        cfg.stream = 0;
        cudaLaunchAttribute attr[1];
        attr[0].id = cudaLaunchAttributeProgrammaticStreamSerialization;
        attr[0].val.programmaticStreamSerializationAllowed = 1;
        cfg.attrs = attr;
        cfg.numAttrs = 1;
        cudaLaunchKernelEx(&cfg, knn_kernel, pts);
    }

    // 3) fuse: normal launch -> full stream ordering after knn (the long
    //    pole); precompute finishes ~6x earlier than knn even when shared.
    fuse_kernel<<<NB / FPTS, 128>>>(w_fuse, g3, b3, m3, v3, out);
}